// round 11
// baseline (speedup 1.0000x reference)
#include <cuda_runtime.h>
#include <cstdint>
#include <cstddef>

// ---------------------------------------------------------------------------
// Spiking conv + WTA, Round 11: 2-warp CTA, w-split dual delta^2 grids
// (warp0: w 0-8 -> gridA, warp1: w 9-17 -> gridB; no cross-warp aliasing),
// merged during cumsum. Canonical collision-free event quads, clamp-to-dump
// scatter, Kahan slope, pipelined cumsum. Lane = output channel.
//   r(tau) = tau/16 - (3/32) relu(tau-16w) + (1/32) relu(tau-48w)   (exact)
// ---------------------------------------------------------------------------

#define COUT   32
#define W18    18
#define KS     48
#define TIN    100
#define TOUT   149
#define NSPAT  31
#define THETA  5.4f
#define HROWS  76          // live grid rows per pass
#define GROWS  77          // +1 dump row for clamped / prefetch reads
#define CNTSZ  112         // s_cnt entries (index >101 provably zero)

// event tables, layout [w][o]
__device__ float4   g_t1[W18 * COUT];   // canonical event values v0..v3
__device__ int      g_t2[W18 * COUT];   // packed row offsets r0..r3 (8b each)
__device__ unsigned g_bits[16 * 2 * 64 * 64 * 4];   // spike bitmasks, 2 MB

__global__ void evt_precompute(const float* __restrict__ weight) {
    int idx = blockIdx.x * blockDim.x + threadIdx.x;
    if (idx >= W18 * COUT) return;
    int o = idx & 31;
    int w = idx >> 5;
    double wv = (double)weight[o * W18 + w];

    double p1 = 16.0 * wv;  int n1 = (int)floor(p1) + 1;  double f1 = (double)n1 - p1;
    double p2 = 48.0 * wv;  int n2 = (int)floor(p2) + 1;  double f2 = (double)n2 - p2;
    const double c1 = -3.0 / 32.0, c2 = 1.0 / 32.0;
    double e0 = c1 * f1, e1 = c1 * (1.0 - f1);
    double e2 = c2 * f2, e3 = c2 * (1.0 - f2);

    // canonical quad: strictly increasing distinct rows (merge collisions)
    int r0, r1, r2, r3; double v0, v1, v2, v3;
    if (n2 - n1 >= 2)      { r0=n1; r1=n1+1; r2=n2;   r3=n2+1; v0=e0;    v1=e1;    v2=e2;  v3=e3;  }
    else if (n2 == n1 + 1) { r0=n1; r1=n1+1; r2=n1+2; r3=n1+3; v0=e0;    v1=e1+e2; v2=e3;  v3=0.0; }
    else                   { r0=n1; r1=n1+1; r2=n1+2; r3=n1+3; v0=e0+e2; v1=e1+e3; v2=0.0; v3=0.0; }

    g_t1[idx] = make_float4((float)v0, (float)v1, (float)v2, (float)v3);
    g_t2[idx] = r0 | (r1 << 8) | (r2 << 16) | (r3 << 24);
}

__global__ __launch_bounds__(256)
void binarize_kernel(const float* __restrict__ xin) {
    int wg   = (blockIdx.x * blockDim.x + threadIdx.x) >> 5;
    int lane = threadIdx.x & 31;
    if (wg >= 16 * 2 * 64 * 64) return;
    const float* row = xin + (size_t)wg * TIN;
    unsigned m[4];
#pragma unroll
    for (int seg = 0; seg < 4; ++seg) {
        int t = seg * 32 + lane;
        float v = (t < TIN) ? __ldg(row + t) : 0.f;
        m[seg] = __ballot_sync(0xffffffffu, v != 0.f);
    }
    if (lane == 0)
        *(uint4*)&g_bits[(size_t)wg * 4] = make_uint4(m[0], m[1], m[2], m[3]);
}

__global__ __launch_bounds__(64)
void wta_kernel(float* __restrict__ out) {
    __shared__ float4                 s_gridA4[GROWS * COUT / 4]; // 9856 B
    __shared__ float4                 s_gridB4[GROWS * COUT / 4]; // 9856 B
    __shared__ float                  s_cnt[CNTSZ];
    __shared__ __align__(16) unsigned s_bits[72];
    __shared__ int                    s_rec[8];     // wt0..3, wc0..3

    float* s_gridA = (float*)s_gridA4;
    float* s_gridB = (float*)s_gridB4;

    const int tid  = threadIdx.x;
    const int lane = tid & 31;
    const int wp   = tid >> 5;                       // 0 or 1
    const int bx   = blockIdx.x;                     // n = ox*31 + oy
    const int b    = blockIdx.y;
    const int ox   = bx / NSPAT;
    const int oy   = bx - ox * NSPAT;

    // ---- stage 1 (warp 0): fetch 18 bitmask rows; init cnt / rec ----
    if (wp == 0) {
        if (lane < W18) {
            int i = lane / 9, rem = lane - i * 9, kx = rem / 3, ky = rem - kx * 3;
            size_t rowidx = (((size_t)b * 2 + i) * 64 + (2 * ox + kx)) * 64 + (2 * oy + ky);
            uint4 v = __ldg((const uint4*)&g_bits[rowidx * 4]);
            *(uint4*)&s_bits[lane * 4] = v;
        }
#pragma unroll
        for (int i = lane; i < CNTSZ; i += 32) s_cnt[i] = 0.f;
        if (lane < 8) s_rec[lane] = -1;
    }
    __syncthreads();

    // ---- stage 1b (warp 0): ramp counts cnt[s+2] = (#spikes at s)/16 ----
    if (wp == 0) {
#pragma unroll
        for (int seg = 0; seg < 4; ++seg) {
            int c = 0;
#pragma unroll
            for (int w = 0; w < W18; ++w) c += (int)((s_bits[w * 4 + seg] >> lane) & 1u);
            int s = seg * 32 + lane;
            if (s < TIN) s_cnt[s + 2] = (float)c * 0.0625f;
        }
    }

    float* mygrid = (wp == 0) ? s_gridA : s_gridB;
    float* col    = mygrid + lane;
    const int wbase = wp * 9;

    float a1 = 0.f, c1 = 0.f, a2 = 0.f;     // warp-0 cumsum state
    int dep = 0, k = 0;

#pragma unroll 1
    for (int h = 0; h < 2; ++h) {
        const int lo = h * HROWS;

        // zero own grid (incl. dump row)
        {
            float4 z4 = make_float4(0.f, 0.f, 0.f, 0.f);
            float4* g4 = (wp == 0) ? s_gridA4 : s_gridB4;
#pragma unroll
            for (int i = lane; i < GROWS * COUT / 4; i += 32) g4[i] = z4;
        }
        __syncthreads();

        // per-seg spike prefilter: half0 needs s<=73, half1 needs s>=25
        unsigned segmask[4];
        if (h == 0) {
            segmask[0] = 0xffffffffu; segmask[1] = 0xffffffffu;
            segmask[2] = 0x000003ffu; segmask[3] = 0u;
        } else {
            segmask[0] = 0xfe000000u;
            segmask[1] = 0xffffffffu; segmask[2] = 0xffffffffu;
            segmask[3] = 0xffffffffu;
        }

        // scatter this warp's w-range into its private grid
#pragma unroll 1
        for (int wi = 0; wi < 9; ++wi) {
            int w = wbase + wi;
            float4 ev = __ldg(&g_t1[w * 32 + lane]);
            int    pk = __ldg(&g_t2[w * 32 + lane]);
            int o0 = pk & 255;
            int o1 = (pk >> 8) & 255;
            int o2 = (pk >> 16) & 255;
            int o3 = ((unsigned)pk) >> 24;
#pragma unroll
            for (int seg = 0; seg < 4; ++seg) {
                unsigned m = s_bits[w * 4 + seg] & segmask[seg];
                int sbase = seg * 32 + 1 - lo;       // s+1-lo for bit 0
                while (m) {
                    int bp = __ffs((int)m) - 1;
                    m &= m - 1;
                    int r = sbase + bp;
                    unsigned u0 = min((unsigned)(r + o0), (unsigned)HROWS);
                    unsigned u1 = min((unsigned)(r + o1), (unsigned)HROWS);
                    unsigned u2 = min((unsigned)(r + o2), (unsigned)HROWS);
                    unsigned u3 = min((unsigned)(r + o3), (unsigned)HROWS);
                    float g0 = col[u0 * 32];
                    float g1 = col[u1 * 32];
                    float g2 = col[u2 * 32];
                    float g3 = col[u3 * 32];
                    g0 += ev.x; g1 += ev.y; g2 += ev.z; g3 += ev.w;
                    col[u0 * 32] = g0;
                    col[u1 * 32] = g1;
                    col[u2 * 32] = g2;
                    col[u3 * 32] = g3;
                }
            }
        }
        __syncthreads();

        // warp 0: double cumsum (merge A+B+cnt) + ballot-gated WTA
        if (wp == 0) {
            const int tend = (h == 0) ? HROWS : TOUT;
            float v = s_gridA[lane] + s_gridB[lane] + s_cnt[min(lo, 108)];
#pragma unroll 1
            for (int t = lo; t < tend; ++t) {
                int rn = (t + 1 - lo) * 32 + lane;    // prefetch next row
                float vn = s_gridA[rn] + s_gridB[rn] + s_cnt[min(t + 1, 108)];
                float y  = v - c1;
                float tt = a1 + y;
                c1 = (tt - a1) - y;
                a1 = tt;
                a2 += (a1 - c1);
                if (dep == 0) {
                    unsigned fm = __ballot_sync(0xffffffffu, a2 > THETA);
                    if (fm) {
                        float bv = a2; int bi = lane;
#pragma unroll
                        for (int off = 16; off; off >>= 1) {
                            float ov = __shfl_xor_sync(0xffffffffu, bv, off);
                            int   oi = __shfl_xor_sync(0xffffffffu, bi, off);
                            if (ov > bv || (ov == bv && oi < bi)) { bv = ov; bi = oi; }
                        }
                        if (lane == 0) { s_rec[k] = t; s_rec[4 + k] = bi; }
                        ++k;
                        dep = KS;
                    }
                }
                dep = dep > 0 ? dep - 1 : 0;
                v = vn;
            }
        }
        __syncthreads();
    }

    // ---- output: warps split channel range; every element written ----
    const int wt0 = s_rec[0], wt1 = s_rec[1], wt2 = s_rec[2], wt3 = s_rec[3];
    const int wc0 = s_rec[4], wc1 = s_rec[5], wc2 = s_rec[6], wc3 = s_rec[7];
#pragma unroll
    for (int q = 0; q < 5; ++q) {
        int t = q * 32 + lane;
        if (t < TOUT) {
            int wv = -2;
            if (t == wt0) wv = wc0;
            if (t == wt1) wv = wc1;
            if (t == wt2) wv = wc2;
            if (t == wt3) wv = wc3;
            float* obase = out + ((size_t)b * 32 * (NSPAT * NSPAT) + bx) * TOUT + t;
#pragma unroll 1
            for (int oc = wp * 16; oc < wp * 16 + 16; ++oc)
                obase[(size_t)oc * (NSPAT * NSPAT) * TOUT] = (wv == oc) ? 1.f : 0.f;
        }
    }
}

extern "C" void kernel_launch(void* const* d_in, const int* in_sizes, int n_in,
                              void* d_out, int out_size) {
    const float* spikes = (const float*)d_in[0];
    const float* weight = (const float*)d_in[1];
    if (n_in >= 2 && in_sizes[0] == 576) {     // defensive input identification
        spikes = (const float*)d_in[1];
        weight = (const float*)d_in[0];
    }

    evt_precompute<<<3, 192>>>(weight);
    binarize_kernel<<<16 * 2 * 64 * 64 / 8, 256>>>(spikes);

    dim3 grid(NSPAT * NSPAT, 16);   // (n, batch)
    wta_kernel<<<grid, 64>>>((float*)d_out);
}

// round 13
// speedup vs baseline: 1.1695x; 1.1695x over previous
#include <cuda_runtime.h>
#include <cstdint>
#include <cstddef>

// ---------------------------------------------------------------------------
// Spiking conv + WTA, Round 13: round-12 with the clamp-path bug fixed
// (u1/u3 derived from unclamped rows; round 12 lost events whose first row
// fell below the window but whose +1 row was live).
// Single-warp CTA, 76-row x 2-pass delta^2 grid, canonical event quads,
// clamp-to-dump scatter w/ warp-uniform interior fast path, Kahan slope,
// 2x-unrolled pipelined cumsum. Lane = output channel.
//   r(tau) = tau/16 - (3/32) relu(tau-16w) + (1/32) relu(tau-48w)   (exact)
// ---------------------------------------------------------------------------

#define COUT   32
#define W18    18
#define KS     48
#define TIN    100
#define TOUT   149
#define NSPAT  31
#define THETA  5.4f
#define HROWS  76          // live grid rows per pass
#define GROWS  77          // +1 dump row for clamped / prefetch reads
#define CNTSZ  112         // s_cnt entries (index >101 provably zero)

// event tables, layout [w][o]
__device__ float4   g_t1[W18 * COUT];   // canonical event values v0..v3
__device__ int      g_t2[W18 * COUT];   // packed row offsets r0..r3 (8b each)
__device__ unsigned g_bits[16 * 2 * 64 * 64 * 4];   // spike bitmasks, 2 MB

__global__ void evt_precompute(const float* __restrict__ weight) {
    int idx = blockIdx.x * blockDim.x + threadIdx.x;
    if (idx >= W18 * COUT) return;
    int o = idx & 31;
    int w = idx >> 5;
    double wv = (double)weight[o * W18 + w];

    double p1 = 16.0 * wv;  int n1 = (int)floor(p1) + 1;  double f1 = (double)n1 - p1;
    double p2 = 48.0 * wv;  int n2 = (int)floor(p2) + 1;  double f2 = (double)n2 - p2;
    const double c1 = -3.0 / 32.0, c2 = 1.0 / 32.0;
    double e0 = c1 * f1, e1 = c1 * (1.0 - f1);
    double e2 = c2 * f2, e3 = c2 * (1.0 - f2);

    // canonical quad: strictly increasing distinct rows (merge collisions)
    int r0, r1, r2, r3; double v0, v1, v2, v3;
    if (n2 - n1 >= 2)      { r0=n1; r1=n1+1; r2=n2;   r3=n2+1; v0=e0;    v1=e1;    v2=e2;  v3=e3;  }
    else if (n2 == n1 + 1) { r0=n1; r1=n1+1; r2=n1+2; r3=n1+3; v0=e0;    v1=e1+e2; v2=e3;  v3=0.0; }
    else                   { r0=n1; r1=n1+1; r2=n1+2; r3=n1+3; v0=e0+e2; v1=e1+e3; v2=0.0; v3=0.0; }

    g_t1[idx] = make_float4((float)v0, (float)v1, (float)v2, (float)v3);
    g_t2[idx] = r0 | (r1 << 8) | (r2 << 16) | (r3 << 24);
}

__global__ __launch_bounds__(256)
void binarize_kernel(const float* __restrict__ xin) {
    int wg   = (blockIdx.x * blockDim.x + threadIdx.x) >> 5;
    int lane = threadIdx.x & 31;
    if (wg >= 16 * 2 * 64 * 64) return;
    const float* row = xin + (size_t)wg * TIN;
    unsigned m[4];
#pragma unroll
    for (int seg = 0; seg < 4; ++seg) {
        int t = seg * 32 + lane;
        float v = (t < TIN) ? __ldg(row + t) : 0.f;
        m[seg] = __ballot_sync(0xffffffffu, v != 0.f);
    }
    if (lane == 0)
        *(uint4*)&g_bits[(size_t)wg * 4] = make_uint4(m[0], m[1], m[2], m[3]);
}

// one cumsum+WTA step: updates v,a1,c1,a2,dep,k and win records
__device__ __forceinline__ void cum_step(
    const float* s_grid, const float* s_cnt, int t, int lo, int lane,
    float& v, float& a1, float& c1, float& a2, int& dep, int& k,
    int& wt0, int& wt1, int& wt2, int& wt3,
    int& wc0, int& wc1, int& wc2, int& wc3)
{
    // prefetch next row (edge reads land in dump row / zero cnt tail)
    float vn = s_grid[(t + 1 - lo) * 32 + lane] + s_cnt[min(t + 1, 108)];
    float y  = v - c1;
    float tt = a1 + y;
    c1 = (tt - a1) - y;
    a1 = tt;
    a2 += (a1 - c1);
    if (dep == 0) {
        unsigned fm = __ballot_sync(0xffffffffu, a2 > THETA);
        if (fm) {
            float bv = a2; int bi = lane;
#pragma unroll
            for (int off = 16; off; off >>= 1) {
                float ov = __shfl_xor_sync(0xffffffffu, bv, off);
                int   oi = __shfl_xor_sync(0xffffffffu, bi, off);
                if (ov > bv || (ov == bv && oi < bi)) { bv = ov; bi = oi; }
            }
            if      (k == 0) { wt0 = t; wc0 = bi; }
            else if (k == 1) { wt1 = t; wc1 = bi; }
            else if (k == 2) { wt2 = t; wc2 = bi; }
            else             { wt3 = t; wc3 = bi; }
            ++k;
            dep = KS;
        }
    }
    dep = dep > 0 ? dep - 1 : 0;
    v = vn;
}

__global__ __launch_bounds__(32)
void wta_kernel(float* __restrict__ out) {
    __shared__ float4                 s_grid4[GROWS * COUT / 4]; // 9856 B reused
    __shared__ float                  s_cnt[CNTSZ];              // ramp d2
    __shared__ __align__(16) unsigned s_bits[72];                // 18 rows x 4

    float* s_grid = (float*)s_grid4;

    const int lane = threadIdx.x;
    const int bx   = blockIdx.x;                     // n = ox*31 + oy
    const int b    = blockIdx.y;
    const int ox   = bx / NSPAT;
    const int oy   = bx - ox * NSPAT;

    // ---- stage 1: fetch 18 bitmask rows (one LDG.128 per active lane) ----
    if (lane < W18) {
        int i = lane / 9, rem = lane - i * 9, kx = rem / 3, ky = rem - kx * 3;
        size_t rowidx = (((size_t)b * 2 + i) * 64 + (2 * ox + kx)) * 64 + (2 * oy + ky);
        uint4 v = __ldg((const uint4*)&g_bits[rowidx * 4]);
        *(uint4*)&s_bits[lane * 4] = v;
    }
#pragma unroll
    for (int i = lane; i < CNTSZ; i += 32) s_cnt[i] = 0.f;
    __syncwarp();

    // ---- stage 1b: shared-ramp counts: cnt[s+2] = (#spikes at s)/16 ----
#pragma unroll
    for (int seg = 0; seg < 4; ++seg) {
        int c = 0;
#pragma unroll
        for (int w = 0; w < W18; ++w) c += (int)((s_bits[w * 4 + seg] >> lane) & 1u);
        int s = seg * 32 + lane;
        if (s < TIN) s_cnt[s + 2] = (float)c * 0.0625f;
    }
    __syncwarp();

    // ---- per-half: zero grid, scatter events, cumsum + WTA ----
    float* col = s_grid + lane;
    float a1 = 0.f, c1 = 0.f, a2 = 0.f;
    int dep = 0, k = 0;
    int wt0 = -1, wt1 = -1, wt2 = -1, wt3 = -1;
    int wc0 = 0, wc1 = 0, wc2 = 0, wc3 = 0;

#pragma unroll 1
    for (int h = 0; h < 2; ++h) {
        const int lo = h * HROWS;

        // zero grid (incl. dump row)
        {
            float4 z4 = make_float4(0.f, 0.f, 0.f, 0.f);
#pragma unroll
            for (int i = lane; i < GROWS * COUT / 4; i += 32) s_grid4[i] = z4;
        }
        __syncwarp();

        // per-seg spike prefilter (clamp is the correctness guard):
        // half0 needs s<=73, half1 needs s>=25
        unsigned segmask[4];
        if (h == 0) {
            segmask[0] = 0xffffffffu; segmask[1] = 0xffffffffu;
            segmask[2] = 0x000003ffu; segmask[3] = 0u;
        } else {
            segmask[0] = 0xfe000000u;
            segmask[1] = 0xffffffffu; segmask[2] = 0xffffffffu;
            segmask[3] = 0xffffffffu;
        }

        // scatter canonical event quads. r = s+1-lo is WARP-UNIFORM:
        //   r in [0,26] -> all lanes' rows in-array (o0>=1, o3<=50 -> <=76)
        //   otherwise   -> clamp each row INDEPENDENTLY to dump row
#pragma unroll 2
        for (int w = 0; w < W18; ++w) {
            float4 ev = __ldg(&g_t1[w * 32 + lane]);
            int    pk = __ldg(&g_t2[w * 32 + lane]);
            int o0 = pk & 255;
            int o2 = (pk >> 16) & 255;
#pragma unroll
            for (int seg = 0; seg < 4; ++seg) {
                unsigned m = s_bits[w * 4 + seg] & segmask[seg];
                int sbase = seg * 32 + 1 - lo;       // s+1-lo for bit 0
                while (m) {
                    int bp = __ffs((int)m) - 1;
                    m &= m - 1;
                    int r = sbase + bp;              // warp-uniform
                    if ((unsigned)r <= 26u) {
                        // interior fast path: rows r+o0, r+o0+1, r+o2, r+o2+1
                        float* p0 = col + (r + o0) * 32;
                        float* p2 = col + (r + o2) * 32;
                        float g0 = p0[0], g1 = p0[32], g2 = p2[0], g3 = p2[32];
                        g0 += ev.x; g1 += ev.y; g2 += ev.z; g3 += ev.w;
                        p0[0] = g0; p0[32] = g1; p2[0] = g2; p2[32] = g3;
                    } else {
                        // FIX vs round 12: clamp each row from its UNCLAMPED
                        // index (u1 from r+o0+1, u3 from r+o2+1), so an event
                        // pair straddling the window lower edge keeps its
                        // live member.
                        unsigned u0 = min((unsigned)(r + o0),     (unsigned)HROWS);
                        unsigned u1 = min((unsigned)(r + o0 + 1), (unsigned)HROWS);
                        unsigned u2 = min((unsigned)(r + o2),     (unsigned)HROWS);
                        unsigned u3 = min((unsigned)(r + o2 + 1), (unsigned)HROWS);
                        float g0 = col[u0 * 32];
                        float g1 = col[u1 * 32];
                        float g2 = col[u2 * 32];
                        float g3 = col[u3 * 32];
                        g0 += ev.x; g1 += ev.y; g2 += ev.z; g3 += ev.w;
                        col[u0 * 32] = g0;
                        col[u1 * 32] = g1;
                        col[u2 * 32] = g2;
                        col[u3 * 32] = g3;
                    }
                }
            }
        }
        __syncwarp();

        // double cumsum + ballot-gated WTA, 2x unrolled, pipelined row fetch
        const int tend = (h == 0) ? HROWS : TOUT;
        float v = s_grid[lane] + s_cnt[min(lo, 108)];
        int t = lo;
#pragma unroll 1
        for (; t + 1 < tend; t += 2) {
            cum_step(s_grid, s_cnt, t,     lo, lane, v, a1, c1, a2, dep, k,
                     wt0, wt1, wt2, wt3, wc0, wc1, wc2, wc3);
            cum_step(s_grid, s_cnt, t + 1, lo, lane, v, a1, c1, a2, dep, k,
                     wt0, wt1, wt2, wt3, wc0, wc1, wc2, wc3);
        }
        if (t < tend)
            cum_step(s_grid, s_cnt, t, lo, lane, v, a1, c1, a2, dep, k,
                     wt0, wt1, wt2, wt3, wc0, wc1, wc2, wc3);
        __syncwarp();
    }

    // ---- output: every element written, coalesced 128B per (oc, q) ----
    float* obase0 = out + ((size_t)b * 32 * (NSPAT * NSPAT) + bx) * TOUT;
#pragma unroll
    for (int q = 0; q < 5; ++q) {
        int t = q * 32 + lane;
        if (t < TOUT) {
            int wv = -1;
            if (t == wt0) wv = wc0;
            if (t == wt1) wv = wc1;
            if (t == wt2) wv = wc2;
            if (t == wt3) wv = wc3;
            float* obase = obase0 + t;
#pragma unroll 1
            for (int oc = 0; oc < 32; ++oc)
                obase[(size_t)oc * (NSPAT * NSPAT) * TOUT] = (wv == oc) ? 1.f : 0.f;
        }
    }
}

extern "C" void kernel_launch(void* const* d_in, const int* in_sizes, int n_in,
                              void* d_out, int out_size) {
    const float* spikes = (const float*)d_in[0];
    const float* weight = (const float*)d_in[1];
    if (n_in >= 2 && in_sizes[0] == 576) {     // defensive input identification
        spikes = (const float*)d_in[1];
        weight = (const float*)d_in[0];
    }

    evt_precompute<<<3, 192>>>(weight);
    binarize_kernel<<<16 * 2 * 64 * 64 / 8, 256>>>(spikes);

    dim3 grid(NSPAT * NSPAT, 16);   // (n, batch)
    wta_kernel<<<grid, 32>>>((float*)d_out);
}

// round 14
// speedup vs baseline: 1.2726x; 1.0881x over previous
#include <cuda_runtime.h>
#include <cstdint>
#include <cstddef>

// ---------------------------------------------------------------------------
// Spiking conv + WTA, Round 14: exact round-10 structure (single-warp CTA,
// 76-row x 2-pass delta^2 grid, canonical event quads, clamp-to-dump scatter,
// Kahan slope, pipelined cumsum) with:
//   (1) ramp counts folded into the grid FILL (cumsum step = 1 LDS),
//   (2) evt_precompute merged into binarize (concurrent, one launch less).
// One 32-thread CTA per (b,ox,oy); lane = output channel.
//   r(tau) = tau/16 - (3/32) relu(tau-16w) + (1/32) relu(tau-48w)   (exact)
// ---------------------------------------------------------------------------

#define COUT   32
#define W18    18
#define KS     48
#define TIN    100
#define TOUT   149
#define NSPAT  31
#define THETA  5.4f
#define HROWS  76          // live grid rows per pass
#define GROWS  77          // +1 dump row for clamped / prefetch reads
#define CNTSZ  112         // s_cnt entries (index >101 provably zero)
#define NB_BIN 16384       // binarize blocks: 16*2*64*64 rows / 8 per block

// event tables, layout [w][o]
__device__ float4   g_t1[W18 * COUT];   // canonical event values v0..v3
__device__ int      g_t2[W18 * COUT];   // packed row offsets r0..r3 (8b each)
__device__ unsigned g_bits[16 * 2 * 64 * 64 * 4];   // spike bitmasks, 2 MB

// merged prep: blocks [0, NB_BIN) binarize spikes; blocks >= NB_BIN build
// the event tables (runs concurrently with the DRAM-bound binarize).
__global__ __launch_bounds__(256)
void prep_kernel(const float* __restrict__ xin, const float* __restrict__ weight) {
    if (blockIdx.x < NB_BIN) {
        int wg   = (blockIdx.x * blockDim.x + threadIdx.x) >> 5;
        int lane = threadIdx.x & 31;
        const float* row = xin + (size_t)wg * TIN;
        unsigned m[4];
#pragma unroll
        for (int seg = 0; seg < 4; ++seg) {
            int t = seg * 32 + lane;
            float v = (t < TIN) ? __ldg(row + t) : 0.f;
            m[seg] = __ballot_sync(0xffffffffu, v != 0.f);
        }
        if (lane == 0)
            *(uint4*)&g_bits[(size_t)wg * 4] = make_uint4(m[0], m[1], m[2], m[3]);
    } else {
        int idx = (blockIdx.x - NB_BIN) * 256 + threadIdx.x;
        if (idx >= W18 * COUT) return;
        int o = idx & 31;
        int w = idx >> 5;
        double wv = (double)weight[o * W18 + w];

        double p1 = 16.0 * wv;  int n1 = (int)floor(p1) + 1;  double f1 = (double)n1 - p1;
        double p2 = 48.0 * wv;  int n2 = (int)floor(p2) + 1;  double f2 = (double)n2 - p2;
        const double c1 = -3.0 / 32.0, c2 = 1.0 / 32.0;
        double e0 = c1 * f1, e1 = c1 * (1.0 - f1);
        double e2 = c2 * f2, e3 = c2 * (1.0 - f2);

        // canonical quad: strictly increasing distinct rows (merge collisions)
        int r0, r1, r2, r3; double v0, v1, v2, v3;
        if (n2 - n1 >= 2)      { r0=n1; r1=n1+1; r2=n2;   r3=n2+1; v0=e0;    v1=e1;    v2=e2;  v3=e3;  }
        else if (n2 == n1 + 1) { r0=n1; r1=n1+1; r2=n1+2; r3=n1+3; v0=e0;    v1=e1+e2; v2=e3;  v3=0.0; }
        else                   { r0=n1; r1=n1+1; r2=n1+2; r3=n1+3; v0=e0+e2; v1=e1+e3; v2=0.0; v3=0.0; }

        g_t1[idx] = make_float4((float)v0, (float)v1, (float)v2, (float)v3);
        g_t2[idx] = r0 | (r1 << 8) | (r2 << 16) | (r3 << 24);
    }
}

__global__ __launch_bounds__(32)
void wta_kernel(float* __restrict__ out) {
    __shared__ float4                 s_grid4[GROWS * COUT / 4]; // 9856 B reused
    __shared__ float                  s_cnt[CNTSZ];              // ramp d2
    __shared__ __align__(16) unsigned s_bits[72];                // 18 rows x 4

    float* s_grid = (float*)s_grid4;

    const int lane = threadIdx.x;
    const int bx   = blockIdx.x;                     // n = ox*31 + oy
    const int b    = blockIdx.y;
    const int ox   = bx / NSPAT;
    const int oy   = bx - ox * NSPAT;

    // ---- stage 1: fetch 18 bitmask rows (one LDG.128 per active lane) ----
    if (lane < W18) {
        int i = lane / 9, rem = lane - i * 9, kx = rem / 3, ky = rem - kx * 3;
        size_t rowidx = (((size_t)b * 2 + i) * 64 + (2 * ox + kx)) * 64 + (2 * oy + ky);
        uint4 v = __ldg((const uint4*)&g_bits[rowidx * 4]);
        *(uint4*)&s_bits[lane * 4] = v;
    }
#pragma unroll
    for (int i = lane; i < CNTSZ; i += 32) s_cnt[i] = 0.f;
    __syncwarp();

    // ---- stage 1b: shared-ramp counts: cnt[s+2] = (#spikes at s)/16 ----
#pragma unroll
    for (int seg = 0; seg < 4; ++seg) {
        int c = 0;
#pragma unroll
        for (int w = 0; w < W18; ++w) c += (int)((s_bits[w * 4 + seg] >> lane) & 1u);
        int s = seg * 32 + lane;
        if (s < TIN) s_cnt[s + 2] = (float)c * 0.0625f;
    }
    __syncwarp();

    // ---- per-half: cnt-fill grid, scatter events, cumsum + WTA ----
    float* col = s_grid + lane;
    float a1 = 0.f, c1 = 0.f, a2 = 0.f;
    int dep = 0, k = 0;
    int wt0 = -1, wt1 = -1, wt2 = -1, wt3 = -1;
    int wc0 = 0, wc1 = 0, wc2 = 0, wc3 = 0;

#pragma unroll 1
    for (int h = 0; h < 2; ++h) {
        const int lo = h * HROWS;

        // FILL grid row r with its ramp value cnt[lo+r] (dump row: value
        // irrelevant, never read live). Replaces zero-fill + per-step cnt add.
#pragma unroll
        for (int i = lane; i < GROWS * COUT / 4; i += 32) {
            int row = i >> 3;                        // 8 float4 per row
            float c = s_cnt[min(lo + row, 108)];
            s_grid4[i] = make_float4(c, c, c, c);
        }
        __syncwarp();

        // per-seg spike prefilter (clamp is the correctness guard):
        // half0 needs s<=73, half1 needs s>=25
        unsigned segmask[4];
        if (h == 0) {
            segmask[0] = 0xffffffffu; segmask[1] = 0xffffffffu;
            segmask[2] = 0x000003ffu; segmask[3] = 0u;
        } else {
            segmask[0] = 0xfe000000u;
            segmask[1] = 0xffffffffu; segmask[2] = 0xffffffffu;
            segmask[3] = 0xffffffffu;
        }

        // scatter canonical event quads: batched LDSx4 / FADDx4 / STSx4,
        // out-of-window rows clamped (independently) to dump row.
#pragma unroll 2
        for (int w = 0; w < W18; ++w) {
            float4 ev = __ldg(&g_t1[w * 32 + lane]);
            int    pk = __ldg(&g_t2[w * 32 + lane]);
            int o0 = pk & 255;
            int o1 = (pk >> 8) & 255;
            int o2 = (pk >> 16) & 255;
            int o3 = ((unsigned)pk) >> 24;
#pragma unroll
            for (int seg = 0; seg < 4; ++seg) {
                unsigned m = s_bits[w * 4 + seg] & segmask[seg];
                int sbase = seg * 32 + 1 - lo;       // s+1-lo for bit 0
                while (m) {
                    int bp = __ffs((int)m) - 1;
                    m &= m - 1;
                    int r = sbase + bp;
                    unsigned u0 = min((unsigned)(r + o0), (unsigned)HROWS);
                    unsigned u1 = min((unsigned)(r + o1), (unsigned)HROWS);
                    unsigned u2 = min((unsigned)(r + o2), (unsigned)HROWS);
                    unsigned u3 = min((unsigned)(r + o3), (unsigned)HROWS);
                    float g0 = col[u0 * 32];
                    float g1 = col[u1 * 32];
                    float g2 = col[u2 * 32];
                    float g3 = col[u3 * 32];
                    g0 += ev.x; g1 += ev.y; g2 += ev.z; g3 += ev.w;
                    col[u0 * 32] = g0;
                    col[u1 * 32] = g1;
                    col[u2 * 32] = g2;
                    col[u3 * 32] = g3;
                }
            }
        }
        __syncwarp();

        // double cumsum + ballot-gated WTA, pipelined row fetch (1 LDS/step).
        // Kahan compensation: corrected slope = a1 - c1.
        const int tend = (h == 0) ? HROWS : TOUT;
        float v = s_grid[lane];
#pragma unroll 1
        for (int t = lo; t < tend; ++t) {
            float vn = s_grid[(t + 1 - lo) * 32 + lane];   // edge -> dump row
            float y  = v - c1;
            float tt = a1 + y;
            c1 = (tt - a1) - y;
            a1 = tt;
            a2 += (a1 - c1);
            if (dep == 0) {
                unsigned fm = __ballot_sync(0xffffffffu, a2 > THETA);
                if (fm) {
                    float bv = a2; int bi = lane;
#pragma unroll
                    for (int off = 16; off; off >>= 1) {
                        float ov = __shfl_xor_sync(0xffffffffu, bv, off);
                        int   oi = __shfl_xor_sync(0xffffffffu, bi, off);
                        if (ov > bv || (ov == bv && oi < bi)) { bv = ov; bi = oi; }
                    }
                    if      (k == 0) { wt0 = t; wc0 = bi; }
                    else if (k == 1) { wt1 = t; wc1 = bi; }
                    else if (k == 2) { wt2 = t; wc2 = bi; }
                    else             { wt3 = t; wc3 = bi; }
                    ++k;
                    dep = KS;
                }
            }
            dep = dep > 0 ? dep - 1 : 0;
            v = vn;
        }
        __syncwarp();
    }

    // ---- output: every element written, coalesced 128B per (oc, q) ----
    float* obase0 = out + ((size_t)b * 32 * (NSPAT * NSPAT) + bx) * TOUT;
#pragma unroll
    for (int q = 0; q < 5; ++q) {
        int t = q * 32 + lane;
        if (t < TOUT) {
            int wv = -1;
            if (t == wt0) wv = wc0;
            if (t == wt1) wv = wc1;
            if (t == wt2) wv = wc2;
            if (t == wt3) wv = wc3;
            float* obase = obase0 + t;
#pragma unroll 1
            for (int oc = 0; oc < 32; ++oc)
                obase[(size_t)oc * (NSPAT * NSPAT) * TOUT] = (wv == oc) ? 1.f : 0.f;
        }
    }
}

extern "C" void kernel_launch(void* const* d_in, const int* in_sizes, int n_in,
                              void* d_out, int out_size) {
    const float* spikes = (const float*)d_in[0];
    const float* weight = (const float*)d_in[1];
    if (n_in >= 2 && in_sizes[0] == 576) {     // defensive input identification
        spikes = (const float*)d_in[1];
        weight = (const float*)d_in[0];
    }

    prep_kernel<<<NB_BIN + 3, 256>>>(spikes, weight);

    dim3 grid(NSPAT * NSPAT, 16);   // (n, batch)
    wta_kernel<<<grid, 32>>>((float*)d_out);
}

// round 15
// speedup vs baseline: 1.3294x; 1.0446x over previous
#include <cuda_runtime.h>
#include <cstdint>
#include <cstddef>

// ---------------------------------------------------------------------------
// Spiking conv + WTA, Round 15: R14 structure (single-warp CTA, 76-row x
// 2-pass delta^2 grid, canonical event quads, clamp-to-dump scatter, Kahan
// slope, cnt-filled grid, pipelined cumsum) with an instruction diet:
//   (1) output = unconditional zero-fill + <=4 winner pokes (no selects),
//   (2) s_bits fetched via one LDS.128 per w in the scatter loop,
//   (3) CNTSZ=160 -> clamp-free grid fill,
//   (4) binarize: block=8 rows, float4-coalesced, smem atomicOr assembly.
// One 32-thread CTA per (b,ox,oy); lane = output channel.
//   r(tau) = tau/16 - (3/32) relu(tau-16w) + (1/32) relu(tau-48w)   (exact)
// ---------------------------------------------------------------------------

#define COUT   32
#define W18    18
#define KS     48
#define TIN    100
#define TOUT   149
#define NSPAT  31
#define THETA  5.4f
#define HROWS  76          // live grid rows per pass
#define GROWS  77          // +1 dump row for clamped / prefetch reads
#define CNTSZ  160         // ramp array; indices 102..159 provably zero
#define NROWS  (16 * 2 * 64 * 64)
#define NB_BIN (NROWS / 8) // binarize blocks: 8 input rows per block

// event tables, layout [w][o]
__device__ float4   g_t1[W18 * COUT];   // canonical event values v0..v3
__device__ int      g_t2[W18 * COUT];   // packed row offsets r0..r3 (8b each)
__device__ unsigned g_bits[NROWS * 4];  // spike bitmasks, 2 MB

// merged prep: blocks [0, NB_BIN) binarize spikes (8 rows = 3200 B contiguous
// per block, float4 loads, smem atomicOr bit assembly — order-independent);
// blocks >= NB_BIN build the event tables (concurrent with binarize).
__global__ __launch_bounds__(256)
void prep_kernel(const float* __restrict__ xin, const float* __restrict__ weight) {
    if (blockIdx.x < NB_BIN) {
        __shared__ unsigned sm[32];        // 8 rows x 4 words
        int tid = threadIdx.x;
        if (tid < 32) sm[tid] = 0u;
        __syncthreads();
        if (tid < 200) {                   // 200 float4 = 800 floats = 8 rows
            float4 v = __ldg((const float4*)(xin + (size_t)blockIdx.x * 800) + tid);
            int id = tid * 4;
            float vv[4] = {v.x, v.y, v.z, v.w};
#pragma unroll
            for (int j = 0; j < 4; ++j) {
                int idx = id + j;
                int row = idx / 100;
                int t   = idx - row * 100;
                if (vv[j] != 0.f)
                    atomicOr(&sm[(row << 2) + (t >> 5)], 1u << (t & 31));
            }
        }
        __syncthreads();
        if (tid < 32) g_bits[(size_t)blockIdx.x * 32 + tid] = sm[tid];
    } else {
        int idx = (int)(blockIdx.x - NB_BIN) * 256 + threadIdx.x;
        if (idx >= W18 * COUT) return;
        int o = idx & 31;
        int w = idx >> 5;
        double wv = (double)weight[o * W18 + w];

        double p1 = 16.0 * wv;  int n1 = (int)floor(p1) + 1;  double f1 = (double)n1 - p1;
        double p2 = 48.0 * wv;  int n2 = (int)floor(p2) + 1;  double f2 = (double)n2 - p2;
        const double c1 = -3.0 / 32.0, c2 = 1.0 / 32.0;
        double e0 = c1 * f1, e1 = c1 * (1.0 - f1);
        double e2 = c2 * f2, e3 = c2 * (1.0 - f2);

        // canonical quad: strictly increasing distinct rows (merge collisions)
        int r0, r1, r2, r3; double v0, v1, v2, v3;
        if (n2 - n1 >= 2)      { r0=n1; r1=n1+1; r2=n2;   r3=n2+1; v0=e0;    v1=e1;    v2=e2;  v3=e3;  }
        else if (n2 == n1 + 1) { r0=n1; r1=n1+1; r2=n1+2; r3=n1+3; v0=e0;    v1=e1+e2; v2=e3;  v3=0.0; }
        else                   { r0=n1; r1=n1+1; r2=n1+2; r3=n1+3; v0=e0+e2; v1=e1+e3; v2=0.0; v3=0.0; }

        g_t1[idx] = make_float4((float)v0, (float)v1, (float)v2, (float)v3);
        g_t2[idx] = r0 | (r1 << 8) | (r2 << 16) | (r3 << 24);
    }
}

__global__ __launch_bounds__(32)
void wta_kernel(float* __restrict__ out) {
    __shared__ float4                 s_grid4[GROWS * COUT / 4]; // 9856 B reused
    __shared__ float                  s_cnt[CNTSZ];              // ramp d2
    __shared__ __align__(16) unsigned s_bits[72];                // 18 rows x 4

    float* s_grid = (float*)s_grid4;

    const int lane = threadIdx.x;
    const int bx   = blockIdx.x;                     // n = ox*31 + oy
    const int b    = blockIdx.y;
    const int ox   = bx / NSPAT;
    const int oy   = bx - ox * NSPAT;

    // ---- stage 1: fetch 18 bitmask rows (one LDG.128 per active lane) ----
    if (lane < W18) {
        int i = lane / 9, rem = lane - i * 9, kx = rem / 3, ky = rem - kx * 3;
        size_t rowidx = (((size_t)b * 2 + i) * 64 + (2 * ox + kx)) * 64 + (2 * oy + ky);
        uint4 v = __ldg((const uint4*)&g_bits[rowidx * 4]);
        *(uint4*)&s_bits[lane * 4] = v;
    }
#pragma unroll
    for (int i = lane; i < CNTSZ; i += 32) s_cnt[i] = 0.f;
    __syncwarp();

    // ---- stage 1b: shared-ramp counts: cnt[s+2] = (#spikes at s)/16 ----
#pragma unroll
    for (int seg = 0; seg < 4; ++seg) {
        int c = 0;
#pragma unroll
        for (int w = 0; w < W18; ++w) c += (int)((s_bits[w * 4 + seg] >> lane) & 1u);
        int s = seg * 32 + lane;
        if (s < TIN) s_cnt[s + 2] = (float)c * 0.0625f;
    }
    __syncwarp();

    // ---- per-half: cnt-fill grid, scatter events, cumsum + WTA ----
    float* col = s_grid + lane;
    float a1 = 0.f, c1 = 0.f, a2 = 0.f;
    int dep = 0, k = 0;
    int wt0 = -1, wt1 = -1, wt2 = -1, wt3 = -1;
    int wc0 = 0, wc1 = 0, wc2 = 0, wc3 = 0;

#pragma unroll 1
    for (int h = 0; h < 2; ++h) {
        const int lo = h * HROWS;

        // FILL grid row r with its ramp value cnt[lo+r] (clamp-free:
        // lo+row <= 152 < CNTSZ, tail entries are zero).
#pragma unroll
        for (int i = lane; i < GROWS * COUT / 4; i += 32) {
            int row = i >> 3;                        // 8 float4 per row
            float c = s_cnt[lo + row];
            s_grid4[i] = make_float4(c, c, c, c);
        }
        __syncwarp();

        // per-seg spike prefilter (clamp is the correctness guard):
        // half0 needs s<=73, half1 needs s>=25
        unsigned segmask[4];
        if (h == 0) {
            segmask[0] = 0xffffffffu; segmask[1] = 0xffffffffu;
            segmask[2] = 0x000003ffu; segmask[3] = 0u;
        } else {
            segmask[0] = 0xfe000000u;
            segmask[1] = 0xffffffffu; segmask[2] = 0xffffffffu;
            segmask[3] = 0xffffffffu;
        }

        // scatter canonical event quads: batched LDSx4 / FADDx4 / STSx4,
        // out-of-window rows clamped (independently) to dump row.
#pragma unroll 2
        for (int w = 0; w < W18; ++w) {
            float4 ev = __ldg(&g_t1[w * 32 + lane]);
            int    pk = __ldg(&g_t2[w * 32 + lane]);
            int o0 = pk & 255;
            int o1 = (pk >> 8) & 255;
            int o2 = (pk >> 16) & 255;
            int o3 = ((unsigned)pk) >> 24;
            uint4 mw = *(const uint4*)&s_bits[w * 4];   // one LDS.128
            unsigned mm[4] = { mw.x & segmask[0], mw.y & segmask[1],
                               mw.z & segmask[2], mw.w & segmask[3] };
#pragma unroll
            for (int seg = 0; seg < 4; ++seg) {
                unsigned m = mm[seg];
                int sbase = seg * 32 + 1 - lo;       // s+1-lo for bit 0
                while (m) {
                    int bp = __ffs((int)m) - 1;
                    m &= m - 1;
                    int r = sbase + bp;
                    unsigned u0 = min((unsigned)(r + o0), (unsigned)HROWS);
                    unsigned u1 = min((unsigned)(r + o1), (unsigned)HROWS);
                    unsigned u2 = min((unsigned)(r + o2), (unsigned)HROWS);
                    unsigned u3 = min((unsigned)(r + o3), (unsigned)HROWS);
                    float g0 = col[u0 * 32];
                    float g1 = col[u1 * 32];
                    float g2 = col[u2 * 32];
                    float g3 = col[u3 * 32];
                    g0 += ev.x; g1 += ev.y; g2 += ev.z; g3 += ev.w;
                    col[u0 * 32] = g0;
                    col[u1 * 32] = g1;
                    col[u2 * 32] = g2;
                    col[u3 * 32] = g3;
                }
            }
        }
        __syncwarp();

        // double cumsum + ballot-gated WTA, pipelined row fetch (1 LDS/step).
        // Kahan compensation: corrected slope = a1 - c1.
        const int tend = (h == 0) ? HROWS : TOUT;
        float v = s_grid[lane];
#pragma unroll 1
        for (int t = lo; t < tend; ++t) {
            float vn = s_grid[(t + 1 - lo) * 32 + lane];   // edge -> dump row
            float y  = v - c1;
            float tt = a1 + y;
            c1 = (tt - a1) - y;
            a1 = tt;
            a2 += (a1 - c1);
            if (dep == 0) {
                unsigned fm = __ballot_sync(0xffffffffu, a2 > THETA);
                if (fm) {
                    float bv = a2; int bi = lane;
#pragma unroll
                    for (int off = 16; off; off >>= 1) {
                        float ov = __shfl_xor_sync(0xffffffffu, bv, off);
                        int   oi = __shfl_xor_sync(0xffffffffu, bi, off);
                        if (ov > bv || (ov == bv && oi < bi)) { bv = ov; bi = oi; }
                    }
                    if      (k == 0) { wt0 = t; wc0 = bi; }
                    else if (k == 1) { wt1 = t; wc1 = bi; }
                    else if (k == 2) { wt2 = t; wc2 = bi; }
                    else             { wt3 = t; wc3 = bi; }
                    ++k;
                    dep = KS;
                }
            }
            dep = dep > 0 ? dep - 1 : 0;
            v = vn;
        }
        __syncwarp();
    }

    // ---- output: unconditional zero-fill, then <=4 winner pokes ----
    float* obase0 = out + ((size_t)b * 32 * (NSPAT * NSPAT) + bx) * TOUT;
    const size_t ocstride = (size_t)(NSPAT * NSPAT) * TOUT;
#pragma unroll
    for (int q = 0; q < 5; ++q) {
        int t = q * 32 + lane;
        if (t < TOUT) {
            float* p = obase0 + t;
#pragma unroll 1
            for (int oc = 0; oc < 32; ++oc) { *p = 0.f; p += ocstride; }
        }
    }
    __syncwarp();    // memory-orders zero stores before winner pokes
    if (lane < k) {
        int wt = (lane == 0) ? wt0 : (lane == 1) ? wt1 : (lane == 2) ? wt2 : wt3;
        int wc = (lane == 0) ? wc0 : (lane == 1) ? wc1 : (lane == 2) ? wc2 : wc3;
        obase0[(size_t)wc * ocstride + wt] = 1.0f;
    }
}

extern "C" void kernel_launch(void* const* d_in, const int* in_sizes, int n_in,
                              void* d_out, int out_size) {
    const float* spikes = (const float*)d_in[0];
    const float* weight = (const float*)d_in[1];
    if (n_in >= 2 && in_sizes[0] == 576) {     // defensive input identification
        spikes = (const float*)d_in[1];
        weight = (const float*)d_in[0];
    }

    prep_kernel<<<NB_BIN + 3, 256>>>(spikes, weight);

    dim3 grid(NSPAT * NSPAT, 16);   // (n, batch)
    wta_kernel<<<grid, 32>>>((float*)d_out);
}

// round 16
// speedup vs baseline: 1.3733x; 1.0330x over previous
#include <cuda_runtime.h>
#include <cstdint>
#include <cstddef>

// ---------------------------------------------------------------------------
// Spiking conv + WTA, Round 16: R15 + (1) pre-scaled event byte-offsets with
// address-space clamp (u32 .shared asm RMWs), (2) burn-down refractory loop
// in the cumsum. Single-warp CTA per (b,ox,oy); lane = output channel.
//   r(tau) = tau/16 - (3/32) relu(tau-16w) + (1/32) relu(tau-48w)   (exact)
// ---------------------------------------------------------------------------

#define COUT   32
#define W18    18
#define KS     48
#define TIN    100
#define TOUT   149
#define NSPAT  31
#define THETA  5.4f
#define HROWS  76          // live grid rows per pass
#define GROWS  77          // +1 dump row for clamped / prefetch reads
#define CNTSZ  160         // ramp array; indices 102..159 provably zero
#define NROWS  (16 * 2 * 64 * 64)
#define NB_BIN (NROWS / 8) // binarize blocks: 8 input rows per block

// event tables, layout [w][o]
__device__ float4   g_t1[W18 * COUT];    // canonical event values v0..v3
__device__ uint4    g_off[W18 * COUT];   // pre-scaled row offsets r_i*128 (bytes)
__device__ unsigned g_bits[NROWS * 4];   // spike bitmasks, 2 MB

// merged prep: blocks [0, NB_BIN) binarize spikes (8 rows = 3200 B contiguous
// per block, float4 loads, smem atomicOr bit assembly — order-independent);
// blocks >= NB_BIN build the event tables (concurrent with binarize).
__global__ __launch_bounds__(256)
void prep_kernel(const float* __restrict__ xin, const float* __restrict__ weight) {
    if (blockIdx.x < NB_BIN) {
        __shared__ unsigned sm[32];        // 8 rows x 4 words
        int tid = threadIdx.x;
        if (tid < 32) sm[tid] = 0u;
        __syncthreads();
        if (tid < 200) {                   // 200 float4 = 800 floats = 8 rows
            float4 v = __ldg((const float4*)(xin + (size_t)blockIdx.x * 800) + tid);
            int id = tid * 4;
            float vv[4] = {v.x, v.y, v.z, v.w};
#pragma unroll
            for (int j = 0; j < 4; ++j) {
                int idx = id + j;
                int row = idx / 100;
                int t   = idx - row * 100;
                if (vv[j] != 0.f)
                    atomicOr(&sm[(row << 2) + (t >> 5)], 1u << (t & 31));
            }
        }
        __syncthreads();
        if (tid < 32) g_bits[(size_t)blockIdx.x * 32 + tid] = sm[tid];
    } else {
        int idx = (int)(blockIdx.x - NB_BIN) * 256 + threadIdx.x;
        if (idx >= W18 * COUT) return;
        int o = idx & 31;
        int w = idx >> 5;
        double wv = (double)weight[o * W18 + w];

        double p1 = 16.0 * wv;  int n1 = (int)floor(p1) + 1;  double f1 = (double)n1 - p1;
        double p2 = 48.0 * wv;  int n2 = (int)floor(p2) + 1;  double f2 = (double)n2 - p2;
        const double c1 = -3.0 / 32.0, c2 = 1.0 / 32.0;
        double e0 = c1 * f1, e1 = c1 * (1.0 - f1);
        double e2 = c2 * f2, e3 = c2 * (1.0 - f2);

        // canonical quad: strictly increasing distinct rows (merge collisions)
        int r0, r1, r2, r3; double v0, v1, v2, v3;
        if (n2 - n1 >= 2)      { r0=n1; r1=n1+1; r2=n2;   r3=n2+1; v0=e0;    v1=e1;    v2=e2;  v3=e3;  }
        else if (n2 == n1 + 1) { r0=n1; r1=n1+1; r2=n1+2; r3=n1+3; v0=e0;    v1=e1+e2; v2=e3;  v3=0.0; }
        else                   { r0=n1; r1=n1+1; r2=n1+2; r3=n1+3; v0=e0+e2; v1=e1+e3; v2=0.0; v3=0.0; }

        g_t1[idx]  = make_float4((float)v0, (float)v1, (float)v2, (float)v3);
        g_off[idx] = make_uint4((unsigned)(r0 * 128), (unsigned)(r1 * 128),
                                (unsigned)(r2 * 128), (unsigned)(r3 * 128));
    }
}

__global__ __launch_bounds__(32)
void wta_kernel(float* __restrict__ out) {
    __shared__ float4                 s_grid4[GROWS * COUT / 4]; // 9856 B reused
    __shared__ float                  s_cnt[CNTSZ];              // ramp d2
    __shared__ __align__(16) unsigned s_bits[72];                // 18 rows x 4

    float* s_grid = (float*)s_grid4;

    const int lane = threadIdx.x;
    const int bx   = blockIdx.x;                     // n = ox*31 + oy
    const int b    = blockIdx.y;
    const int ox   = bx / NSPAT;
    const int oy   = bx - ox * NSPAT;

    // ---- stage 1: fetch 18 bitmask rows (one LDG.128 per active lane) ----
    if (lane < W18) {
        int i = lane / 9, rem = lane - i * 9, kx = rem / 3, ky = rem - kx * 3;
        size_t rowidx = (((size_t)b * 2 + i) * 64 + (2 * ox + kx)) * 64 + (2 * oy + ky);
        uint4 v = __ldg((const uint4*)&g_bits[rowidx * 4]);
        *(uint4*)&s_bits[lane * 4] = v;
    }
#pragma unroll
    for (int i = lane; i < CNTSZ; i += 32) s_cnt[i] = 0.f;
    __syncwarp();

    // ---- stage 1b: shared-ramp counts: cnt[s+2] = (#spikes at s)/16 ----
#pragma unroll
    for (int seg = 0; seg < 4; ++seg) {
        int c = 0;
#pragma unroll
        for (int w = 0; w < W18; ++w) c += (int)((s_bits[w * 4 + seg] >> lane) & 1u);
        int s = seg * 32 + lane;
        if (s < TIN) s_cnt[s + 2] = (float)c * 0.0625f;
    }
    __syncwarp();

    // u32 shared-space addresses for the scatter RMWs
    const uint32_t colb  = (uint32_t)__cvta_generic_to_shared(s_grid) + (uint32_t)lane * 4u;
    const uint32_t dumpb = colb + (uint32_t)HROWS * 128u;

    float a1 = 0.f, c1 = 0.f, a2 = 0.f;
    int dep = 0, k = 0;
    int wt0 = -1, wt1 = -1, wt2 = -1, wt3 = -1;
    int wc0 = 0, wc1 = 0, wc2 = 0, wc3 = 0;

#pragma unroll 1
    for (int h = 0; h < 2; ++h) {
        const int lo = h * HROWS;

        // FILL grid row r with its ramp value cnt[lo+r] (clamp-free).
#pragma unroll
        for (int i = lane; i < GROWS * COUT / 4; i += 32) {
            int row = i >> 3;                        // 8 float4 per row
            float c = s_cnt[lo + row];
            s_grid4[i] = make_float4(c, c, c, c);
        }
        __syncwarp();

        // per-seg spike prefilter (address clamp is the correctness guard):
        // half0 needs s<=73, half1 needs s>=25
        unsigned segmask[4];
        if (h == 0) {
            segmask[0] = 0xffffffffu; segmask[1] = 0xffffffffu;
            segmask[2] = 0x000003ffu; segmask[3] = 0u;
        } else {
            segmask[0] = 0xfe000000u;
            segmask[1] = 0xffffffffu; segmask[2] = 0xffffffffu;
            segmask[3] = 0xffffffffu;
        }

        // scatter canonical event quads. Per access: IADD + IMNMX (address
        // clamp; negative rows wrap unsigned -> dump) + ld/st.shared.
#pragma unroll 2
        for (int w = 0; w < W18; ++w) {
            float4 ev = __ldg(&g_t1[w * 32 + lane]);
            uint4  of = __ldg(&g_off[w * 32 + lane]);
            const uint32_t A0 = colb + of.x;
            const uint32_t A1 = colb + of.y;
            const uint32_t A2 = colb + of.z;
            const uint32_t A3 = colb + of.w;
            uint4 mw = *(const uint4*)&s_bits[w * 4];   // one LDS.128
            unsigned mm[4] = { mw.x & segmask[0], mw.y & segmask[1],
                               mw.z & segmask[2], mw.w & segmask[3] };
#pragma unroll
            for (int seg = 0; seg < 4; ++seg) {
                unsigned m = mm[seg];
                int sbase = seg * 32 + 1 - lo;       // s+1-lo for bit 0
                while (m) {
                    int bp = __ffs((int)m) - 1;
                    m &= m - 1;
                    uint32_t off = (uint32_t)((sbase + bp) * 128);
                    uint32_t u0 = min(A0 + off, dumpb);
                    uint32_t u1 = min(A1 + off, dumpb);
                    uint32_t u2 = min(A2 + off, dumpb);
                    uint32_t u3 = min(A3 + off, dumpb);
                    float g0, g1, g2, g3;
                    asm volatile("ld.shared.f32 %0,[%1];" : "=f"(g0) : "r"(u0));
                    asm volatile("ld.shared.f32 %0,[%1];" : "=f"(g1) : "r"(u1));
                    asm volatile("ld.shared.f32 %0,[%1];" : "=f"(g2) : "r"(u2));
                    asm volatile("ld.shared.f32 %0,[%1];" : "=f"(g3) : "r"(u3));
                    g0 += ev.x; g1 += ev.y; g2 += ev.z; g3 += ev.w;
                    asm volatile("st.shared.f32 [%0],%1;" :: "r"(u0), "f"(g0));
                    asm volatile("st.shared.f32 [%0],%1;" :: "r"(u1), "f"(g1));
                    asm volatile("st.shared.f32 [%0],%1;" :: "r"(u2), "f"(g2));
                    asm volatile("st.shared.f32 [%0],%1;" :: "r"(u3), "f"(g3));
                }
            }
        }
        __syncwarp();

        // double cumsum + WTA: burn-down loop during refractory (no ballot),
        // ballot-gated argmax otherwise. Kahan: corrected slope = a1 - c1.
        const int tend = (h == 0) ? HROWS : TOUT;
        int t = lo;
        float v = s_grid[lane];
#pragma unroll 1
        while (t < tend) {
            if (dep > 0) {
                int burn = dep < (tend - t) ? dep : (tend - t);
                dep -= burn;
#pragma unroll 1
                for (int j = 0; j < burn; ++j) {
                    float vn = s_grid[(t + 1 - lo) * 32 + lane];
                    float y  = v - c1;
                    float tt = a1 + y;
                    c1 = (tt - a1) - y;
                    a1 = tt;
                    a2 += (a1 - c1);
                    v = vn; ++t;
                }
                continue;
            }
            float vn = s_grid[(t + 1 - lo) * 32 + lane];   // edge -> dump row
            float y  = v - c1;
            float tt = a1 + y;
            c1 = (tt - a1) - y;
            a1 = tt;
            a2 += (a1 - c1);
            unsigned fm = __ballot_sync(0xffffffffu, a2 > THETA);
            if (fm) {
                float bv = a2; int bi = lane;
#pragma unroll
                for (int off = 16; off; off >>= 1) {
                    float ov = __shfl_xor_sync(0xffffffffu, bv, off);
                    int   oi = __shfl_xor_sync(0xffffffffu, bi, off);
                    if (ov > bv || (ov == bv && oi < bi)) { bv = ov; bi = oi; }
                }
                if      (k == 0) { wt0 = t; wc0 = bi; }
                else if (k == 1) { wt1 = t; wc1 = bi; }
                else if (k == 2) { wt2 = t; wc2 = bi; }
                else             { wt3 = t; wc3 = bi; }
                ++k;
                dep = KS - 1;      // burns t+1..t+47; fireable again at t+48
            }
            v = vn; ++t;
        }
        __syncwarp();
    }

    // ---- output: unconditional zero-fill, then <=4 winner pokes ----
    float* obase0 = out + ((size_t)b * 32 * (NSPAT * NSPAT) + bx) * TOUT;
    const size_t ocstride = (size_t)(NSPAT * NSPAT) * TOUT;
#pragma unroll
    for (int q = 0; q < 5; ++q) {
        int t = q * 32 + lane;
        if (t < TOUT) {
            float* p = obase0 + t;
#pragma unroll 1
            for (int oc = 0; oc < 32; ++oc) { *p = 0.f; p += ocstride; }
        }
    }
    __syncwarp();    // memory-orders zero stores before winner pokes
    if (lane < k) {
        int wt = (lane == 0) ? wt0 : (lane == 1) ? wt1 : (lane == 2) ? wt2 : wt3;
        int wc = (lane == 0) ? wc0 : (lane == 1) ? wc1 : (lane == 2) ? wc2 : wt3;
        wc = (lane == 0) ? wc0 : (lane == 1) ? wc1 : (lane == 2) ? wc2 : wc3;
        obase0[(size_t)wc * ocstride + wt] = 1.0f;
    }
}

extern "C" void kernel_launch(void* const* d_in, const int* in_sizes, int n_in,
                              void* d_out, int out_size) {
    const float* spikes = (const float*)d_in[0];
    const float* weight = (const float*)d_in[1];
    if (n_in >= 2 && in_sizes[0] == 576) {     // defensive input identification
        spikes = (const float*)d_in[1];
        weight = (const float*)d_in[0];
    }

    prep_kernel<<<NB_BIN + 3, 256>>>(spikes, weight);

    dim3 grid(NSPAT * NSPAT, 16);   // (n, batch)
    wta_kernel<<<grid, 32>>>((float*)d_out);
}